// round 16
// baseline (speedup 1.0000x reference)
#include <cuda_runtime.h>
#include <cuda_bf16.h>
#include <cuda_fp16.h>
#include <math.h>
#include <cstdint>

#define Bdim 2
#define Ldim 2048
#define Edim 1024
#define Hdim 16
#define Ddim 64
#define NROWS (Bdim * Ldim)  // 4096
#define NBH (Bdim * Hdim)    // 32

// log2(e)^2 folding: C2*d2 inside sqrt gives log2(e)*d directly
#define C2 2.0813689810056077f
#define NEG2C2 (-4.1627379620112154f)

// Scratch (allocation-free rule: __device__ globals)
__device__ unsigned short g_qh[(size_t)NROWS * Edim];       // q proj, bf16, row-major (B,L,E)
__device__ unsigned short g_kh[(size_t)NROWS * Edim];       // k proj, bf16, row-major (B,L,E)
__device__ float g_q2[NBH * Ldim];                // C2 * ||q||^2 (fp32-derived, accumulated)
__device__ float g_k2[NBH * Ldim];                // C2 * ||k||^2
__device__ float g_w[NBH * Ldim];
__device__ float g_vbar[NBH * Edim];              // Σ_k w[bh,k] * V[b,k,:]  (exact fp32)
__device__ float g_ho[Bdim * Edim];
// exp scores, f16, scaled 4096x. k-PERMUTED within each 32-col block:
//   pos = t*8 + ni*2 + j  holds  k = ni*8 + 2t + j
__device__ unsigned short g_e[(size_t)NBH * Ldim * Ldim];

// ======================================================================
// Helpers (plain sm_103 target: mma.sync + cp.async only)
// ======================================================================
__device__ __forceinline__ uint32_t smem_to_u32(const void* smem_ptr) {
    uint32_t addr;
    asm("{ .reg .u64 tmp; cvta.to.shared.u64 tmp, %1; cvt.u32.u64 %0, tmp; }"
        : "=r"(addr) : "l"(smem_ptr));
    return addr;
}
__device__ __forceinline__ void cp_async16(uint32_t s, const void* g) {
    asm volatile("cp.async.cg.shared.global [%0], [%1], 16;" :: "r"(s), "l"(g) : "memory");
}
__device__ __forceinline__ void cp_commit() {
    asm volatile("cp.async.commit_group;" ::: "memory");
}
template <int N>
__device__ __forceinline__ void cp_wait() {
    asm volatile("cp.async.wait_group %0;" :: "n"(N) : "memory");
}
__device__ __forceinline__ uint32_t f2tf(float x) {
    uint32_t r;
    asm("cvt.rna.tf32.f32 %0, %1;" : "=r"(r) : "f"(x));
    return r;
}
__device__ __forceinline__ float fast_sqrt(float x) {
    float r; asm("sqrt.approx.f32 %0, %1;" : "=f"(r) : "f"(x)); return r;
}
// packed f16x2 exp2 — one MUFU op, two results. Arg quantization error is
// incoherent per (q,k) -> averages out in w (verified R7==R8, R9..R15 pass).
__device__ __forceinline__ uint32_t h2_ex2(uint32_t x) {
    uint32_t r;
    asm("ex2.approx.f16x2 %0, %1;" : "=r"(r) : "r"(x));
    return r;
}
__device__ __forceinline__ void mma_tf32(float c[4], const uint32_t a[4], const uint32_t b[2]) {
    asm volatile(
        "mma.sync.aligned.m16n8k8.row.col.f32.tf32.tf32.f32 "
        "{%0,%1,%2,%3}, {%4,%5,%6,%7}, {%8,%9}, {%0,%1,%2,%3};"
        : "+f"(c[0]), "+f"(c[1]), "+f"(c[2]), "+f"(c[3])
        : "r"(a[0]), "r"(a[1]), "r"(a[2]), "r"(a[3]), "r"(b[0]), "r"(b[1]));
}
__device__ __forceinline__ void mma_bf16(float c[4], const uint32_t a[4], const uint32_t b[2]) {
    asm volatile(
        "mma.sync.aligned.m16n8k16.row.col.f32.bf16.bf16.f32 "
        "{%0,%1,%2,%3}, {%4,%5,%6,%7}, {%8,%9}, {%0,%1,%2,%3};"
        : "+f"(c[0]), "+f"(c[1]), "+f"(c[2]), "+f"(c[3])
        : "r"(a[0]), "r"(a[1]), "r"(a[2]), "r"(a[3]), "r"(b[0]), "r"(b[1]));
}

// ======================================================================
// Zero accumulators: g_ho, g_w, g_q2, g_k2, g_vbar (runs FIRST)
// ======================================================================
__global__ void zero_acc_kernel()
{
    int i = blockIdx.x * blockDim.x + threadIdx.x;  // 0..65535
    if (i < Bdim * Edim) g_ho[i] = 0.f;
    if (i < NBH * Edim) g_vbar[i] = 0.f;
    g_w[i] = 0.f;
    g_q2[i] = 0.f;
    g_k2[i] = 0.f;
}

// ======================================================================
// Projection GEMM (mma.sync tf32, inline rna cvt — R10 config).
// ONLY q (z=0) and k (z=1): V projection eliminated algebraically.
// Epilogue writes bf16 row-major + accumulates C2*||.||^2 via atomics.
// ======================================================================
#define PJST 36
#define PJ_TILE_FLOATS (128 * PJST)
#define PJ_BUF_FLOATS (2 * PJ_TILE_FLOATS)
#define PJ_SMEM_BYTES (2 * PJ_BUF_FLOATS * 4 + 1024)

__global__ void __launch_bounds__(256) proj_mma_kernel(
    const float* __restrict__ Q, const float* __restrict__ K,
    const float* __restrict__ Wq, const float* __restrict__ Wk)
{
    extern __shared__ float smem[];
    const uint32_t smem_u32 = smem_to_u32(smem);

    const int z = blockIdx.z;
    const float* __restrict__ X = z ? K : Q;
    const float* __restrict__ W = z ? Wk : Wq;
    const int m0 = blockIdx.x * 128;
    const int n0 = blockIdx.y * 128;

    const int tid = threadIdx.x;
    const int wid = tid >> 5;
    const int lane = tid & 31;
    const int g = lane >> 2;
    const int t = lane & 3;
    const int wm = (wid >> 2) * 64;
    const int wn = (wid & 3) * 32;

    float c[4][4][4];
#pragma unroll
    for (int mi = 0; mi < 4; mi++)
#pragma unroll
        for (int ni = 0; ni < 4; ni++)
#pragma unroll
            for (int r = 0; r < 4; r++) c[mi][ni][r] = 0.f;

    auto load_chunk = [&](int cc) {
        const int k0 = cc * 32;
        uint32_t abase = smem_u32 + (uint32_t)((cc & 1) * PJ_BUF_FLOATS) * 4u;
#pragma unroll
        for (int it = 0; it < 4; it++) {
            int idx = tid + it * 256;
            int row = idx >> 3;
            int q = idx & 7;
            uint32_t soff = (uint32_t)(row * PJST + q * 4) * 4u;
            cp_async16(abase + soff, &X[(size_t)(m0 + row) * Edim + k0 + q * 4]);
            cp_async16(abase + (uint32_t)PJ_TILE_FLOATS * 4u + soff,
                       &W[(size_t)(n0 + row) * Edim + k0 + q * 4]);
        }
        cp_commit();
    };

    load_chunk(0);

    for (int cc = 0; cc < 32; cc++) {
        if (cc + 1 < 32) {
            load_chunk(cc + 1);
            cp_wait<1>();
        } else {
            cp_wait<0>();
        }
        __syncthreads();

        const float* As_ = smem + (cc & 1) * PJ_BUF_FLOATS;
        const float* Bs_ = As_ + PJ_TILE_FLOATS;

#pragma unroll
        for (int ks = 0; ks < 4; ks++) {
            const int k0 = ks * 8;
            uint32_t a[4][4], bf[4][2];
#pragma unroll
            for (int mi = 0; mi < 4; mi++) {
                const float* ap = As_ + (wm + mi * 16 + g) * PJST + k0 + t;
                a[mi][0] = f2tf(ap[0]);
                a[mi][1] = f2tf(ap[8 * PJST]);
                a[mi][2] = f2tf(ap[4]);
                a[mi][3] = f2tf(ap[8 * PJST + 4]);
            }
#pragma unroll
            for (int ni = 0; ni < 4; ni++) {
                const float* bp = Bs_ + (wn + ni * 8 + g) * PJST + k0 + t;
                bf[ni][0] = f2tf(bp[0]);
                bf[ni][1] = f2tf(bp[4]);
            }
#pragma unroll
            for (int mi = 0; mi < 4; mi++)
#pragma unroll
                for (int ni = 0; ni < 4; ni++) mma_tf32(c[mi][ni], a[mi], bf[ni]);
        }
        __syncthreads();
    }

    unsigned short* dst = z ? g_kh : g_qh;
    float* nrm = z ? g_k2 : g_q2;
    float* snorm = smem;  // 256 floats: [row128][head_local]

    if (tid < 256) snorm[tid] = 0.f;

    float rsum[4][2];
#pragma unroll
    for (int mi = 0; mi < 4; mi++) {
#pragma unroll
        for (int half = 0; half < 2; half++) {
            float s = 0.f;
#pragma unroll
            for (int ni = 0; ni < 4; ni++) {
                float v0 = c[mi][ni][half * 2 + 0];
                float v1 = c[mi][ni][half * 2 + 1];
                s = fmaf(v0, v0, s);
                s = fmaf(v1, v1, s);
            }
            rsum[mi][half] = s;
        }
    }
#pragma unroll
    for (int mi = 0; mi < 4; mi++)
#pragma unroll
        for (int half = 0; half < 2; half++) {
            float s = rsum[mi][half];
            s += __shfl_xor_sync(0xffffffffu, s, 1);
            s += __shfl_xor_sync(0xffffffffu, s, 2);
            rsum[mi][half] = s;
        }
    __syncthreads();
    const int hh = wn >> 6;
    if (t == 0) {
#pragma unroll
        for (int mi = 0; mi < 4; mi++)
#pragma unroll
            for (int half = 0; half < 2; half++) {
                int r128 = wm + mi * 16 + half * 8 + g;
                atomicAdd(&snorm[r128 * 2 + hh], rsum[mi][half]);
            }
    }

#pragma unroll
    for (int mi = 0; mi < 4; mi++) {
        int row = m0 + wm + mi * 16 + g;
#pragma unroll
        for (int ni = 0; ni < 4; ni++) {
            int col = n0 + wn + ni * 8 + 2 * t;
            __nv_bfloat162 lo = __float22bfloat162_rn(make_float2(c[mi][ni][0], c[mi][ni][1]));
            __nv_bfloat162 hi = __float22bfloat162_rn(make_float2(c[mi][ni][2], c[mi][ni][3]));
            *(__nv_bfloat162*)&dst[(size_t)row * Edim + col] = lo;
            *(__nv_bfloat162*)&dst[(size_t)(row + 8) * Edim + col] = hi;
        }
    }

    __syncthreads();
    if (tid < 256) {
        int r128 = tid >> 1;
        int row = m0 + r128;
        int b = row >> 11;
        int l = row & 2047;
        int h = (n0 >> 6) + (tid & 1);
        atomicAdd(&nrm[(b * Hdim + h) * Ldim + l], C2 * snorm[tid]);
    }
}

// ======================================================================
// Attention pass A + FUSED pass B tail.
// Main loop (R14 exact): bf16 m16n8k16 QK^T; f16x2-MUFU exp; e stored
// k-permuted with 16B-contiguous uint4 STGs; Z accumulated.
// Tail: invZ kept in smem; the CTA re-reads its OWN 128x2048 e block
// (freshly written -> substantial L2 reuse; CTAs hit tails staggered so
// the memory phase overlaps other CTAs' compute), multiplies by invZ,
// un-permutes, atomicAdds partial w. Former passB kernel is DELETED.
// ======================================================================
#define A_Q_BYTES (128 * 144)
#define A_K_BYTES (128 * 144)
#define A_SMEM_BYTES (A_Q_BYTES + 2 * A_K_BYTES + 512)

__global__ void __launch_bounds__(256, 2) attn_passA_kernel()
{
    extern __shared__ char smc[];
    char* qsc = smc;
    char* ksc = smc + A_Q_BYTES;
    float* zsh = (float*)(smc + A_Q_BYTES + 2 * A_K_BYTES);
    const uint32_t qs_u = smem_to_u32(qsc);
    const uint32_t ks_u = smem_to_u32(ksc);

    const int tid = threadIdx.x;
    const int wid = tid >> 5;
    const int lane = tid & 31;
    const int g = lane >> 2;
    const int t = lane & 3;
    const int wm = (wid >> 2) * 64;
    const int wn = (wid & 3) * 32;
    const int bh = blockIdx.y;
    const int b = bh >> 4;
    const int h = bh & 15;
    const int qbase = blockIdx.x * 128;

    if (tid < 128) zsh[tid] = 0.f;

    const unsigned short* gq = g_qh + (size_t)(b * Ldim + qbase) * Edim + h * Ddim;
    const unsigned short* gk = g_kh + (size_t)(b * Ldim) * Edim + h * Ddim;

#pragma unroll
    for (int it = 0; it < 4; it++) {
        int idx = tid + it * 256;
        int r = idx >> 3;
        int ch = idx & 7;
        cp_async16(qs_u + (uint32_t)(r * 144 + ch * 16), gq + (size_t)r * Edim + ch * 8);
    }
    cp_commit();

    auto load_k = [&](int jt) {
        uint32_t base = ks_u + (uint32_t)((jt & 1) * A_K_BYTES);
#pragma unroll
        for (int it = 0; it < 4; it++) {
            int idx = tid + it * 256;
            int r = idx >> 3;
            int ch = idx & 7;
            cp_async16(base + (uint32_t)(r * 144 + ch * 16),
                       gk + (size_t)(jt * 128 + r) * Edim + ch * 8);
        }
        cp_commit();
    };

    load_k(0);
    cp_wait<1>();
    __syncthreads();

    float q2r[8];
    const float* q2p = g_q2 + bh * Ldim + qbase;
#pragma unroll
    for (int i = 0; i < 8; i++) q2r[i] = q2p[wm + (i >> 1) * 16 + (i & 1) * 8 + g];

    unsigned short* pe0 = g_e + ((size_t)bh * Ldim + qbase + wm + g) * Ldim + wn + t * 8;

    float zloc[8];
#pragma unroll
    for (int i = 0; i < 8; i++) zloc[i] = 0.f;

    for (int jt = 0; jt < 16; jt++) {
        if (jt + 1 < 16) {
            load_k(jt + 1);
            cp_wait<1>();
        } else {
            cp_wait<0>();
        }
        __syncthreads();

        const char* kb = ksc + (jt & 1) * A_K_BYTES;

        float c[4][4][4];
#pragma unroll
        for (int mi = 0; mi < 4; mi++)
#pragma unroll
            for (int ni = 0; ni < 4; ni++)
#pragma unroll
                for (int r = 0; r < 4; r++) c[mi][ni][r] = 0.f;

#pragma unroll
        for (int ks = 0; ks < 4; ks++) {
            uint32_t a[4][4], bf[4][2];
#pragma unroll
            for (int mi = 0; mi < 4; mi++) {
                const char* ap = qsc + (wm + mi * 16 + g) * 144 + ks * 32 + t * 4;
                a[mi][0] = *(const uint32_t*)(ap);
                a[mi][1] = *(const uint32_t*)(ap + 8 * 144);
                a[mi][2] = *(const uint32_t*)(ap + 16);
                a[mi][3] = *(const uint32_t*)(ap + 8 * 144 + 16);
            }
#pragma unroll
            for (int ni = 0; ni < 4; ni++) {
                const char* bp = kb + (wn + ni * 8 + g) * 144 + ks * 32 + t * 4;
                bf[ni][0] = *(const uint32_t*)(bp);
                bf[ni][1] = *(const uint32_t*)(bp + 16);
            }
#pragma unroll
            for (int mi = 0; mi < 4; mi++)
#pragma unroll
                for (int ni = 0; ni < 4; ni++) mma_bf16(c[mi][ni], a[mi], bf[ni]);
        }

        const float* k2p = g_k2 + bh * Ldim + jt * 128;
        unsigned short* pet = pe0 + jt * 128;
        float2 k2c[4];
#pragma unroll
        for (int ni = 0; ni < 4; ni++) k2c[ni] = *(const float2*)&k2p[wn + ni * 8 + 2 * t];
#pragma unroll
        for (int mi = 0; mi < 4; mi++) {
#pragma unroll
            for (int half = 0; half < 2; half++) {
                uint32_t ee4[4];
                float zz = 0.f;
#pragma unroll
                for (int ni = 0; ni < 4; ni++) {
                    float s0 = fmaf(NEG2C2, c[mi][ni][half * 2 + 0], q2r[mi * 2 + half] + k2c[ni].x);
                    float s1 = fmaf(NEG2C2, c[mi][ni][half * 2 + 1], q2r[mi * 2 + half] + k2c[ni].y);
                    float a0 = 12.f - fast_sqrt(fmaxf(s0, 0.f));
                    float a1 = 12.f - fast_sqrt(fmaxf(s1, 0.f));
                    __half2 hh2 = __floats2half2_rn(a0, a1);
                    uint32_t ee = h2_ex2(*(const uint32_t*)&hh2);
                    float2 ef = __half22float2(*(const __half2*)&ee);
                    zz += ef.x + ef.y;
                    ee4[ni] = ee;
                }
                zloc[mi * 2 + half] += zz;
                *(uint4*)(pet + (size_t)(mi * 16 + half * 8) * Ldim) =
                    make_uint4(ee4[0], ee4[1], ee4[2], ee4[3]);
            }
        }
        __syncthreads();
    }

    // Z reduce -> invZ in smem
#pragma unroll
    for (int i = 0; i < 8; i++) {
        float z = zloc[i];
        z += __shfl_xor_sync(0xffffffffu, z, 1);
        z += __shfl_xor_sync(0xffffffffu, z, 2);
        if (t == 0) atomicAdd(&zsh[wm + (i >> 1) * 16 + (i & 1) * 8 + g], z);
    }
    __syncthreads();
    if (tid < 128) zsh[tid] = 1.f / zsh[tid];
    __syncthreads();

    // ---- fused pass-B tail: partial w over this CTA's own e block ----
    // warp wid covers cols [wid*256, wid*256+256); lane reads 8 contiguous
    // permuted positions (16B) per q row. All e stores above are ordered
    // before these loads by the __syncthreads (same-CTA global visibility).
    {
        const int wcol0 = wid * 256;
        const unsigned short* pe =
            g_e + ((size_t)bh * Ldim + qbase) * Ldim + wcol0 + lane * 8;
        float acc[8];
#pragma unroll
        for (int j = 0; j < 8; j++) acc[j] = 0.f;
#pragma unroll 4
        for (int q = 0; q < 128; q++) {
            uint4 raw = *(const uint4*)(pe + (size_t)q * Ldim);
            float iz = zsh[q];
            float2 e0 = __half22float2(*(const __half2*)&raw.x);
            float2 e1 = __half22float2(*(const __half2*)&raw.y);
            float2 e2 = __half22float2(*(const __half2*)&raw.z);
            float2 e3 = __half22float2(*(const __half2*)&raw.w);
            acc[0] = fmaf(e0.x, iz, acc[0]);
            acc[1] = fmaf(e0.y, iz, acc[1]);
            acc[2] = fmaf(e1.x, iz, acc[2]);
            acc[3] = fmaf(e1.y, iz, acc[3]);
            acc[4] = fmaf(e2.x, iz, acc[4]);
            acc[5] = fmaf(e2.y, iz, acc[5]);
            acc[6] = fmaf(e3.x, iz, acc[6]);
            acc[7] = fmaf(e3.y, iz, acc[7]);
        }
        // un-permute: this lane's positions are pos = (lane&3)*8 + j within
        // 32-block (wcol0 + (lane>>2)*32); logical k = (j>>1)*8 + (lane&3)*2 + (j&1)
        const int tloc = lane & 3;
        float* wdst = g_w + bh * Ldim + wcol0 + (lane >> 2) * 32;
#pragma unroll
        for (int j = 0; j < 8; j++) {
            int kk = (j >> 1) * 8 + tloc * 2 + (j & 1);
            atomicAdd(&wdst[kk], acc[j]);
        }
    }
}

// ======================================================================
// vbar[b,h,e] = sum_k w[bh,k] * V[b,k,e]   (raw fp32 V — no projection!)
// ======================================================================
__global__ void __launch_bounds__(256) vbar_kernel(const float* __restrict__ V)
{
    __shared__ float wsh[16][128];
    const int tid = threadIdx.x;
    const int e = blockIdx.x * 256 + tid;
    const int b = blockIdx.y;
    const int k0 = blockIdx.z * 128;

    for (int i = tid; i < 16 * 128; i += 256) {
        int h = i >> 7;
        int kk = i & 127;
        wsh[h][kk] = g_w[(b * Hdim + h) * Ldim + k0 + kk];
    }
    __syncthreads();

    float acc[16];
#pragma unroll
    for (int h = 0; h < 16; h++) acc[h] = 0.f;

    const float* vp = V + ((size_t)(b * Ldim + k0)) * Edim + e;
#pragma unroll 4
    for (int kk = 0; kk < 128; kk++) {
        float v = vp[(size_t)kk * Edim];
#pragma unroll
        for (int h = 0; h < 16; h++) acc[h] = fmaf(wsh[h][kk], v, acc[h]);
    }
#pragma unroll
    for (int h = 0; h < 16; h++)
        atomicAdd(&g_vbar[(b * Hdim + h) * Edim + e], acc[h]);
}

// ======================================================================
// ho[b, h*64+d] = vbar[b,h,:] . Wv[h*64+d,:]   (warp per output, fp32)
// ======================================================================
__global__ void __launch_bounds__(256) ho_kernel(const float* __restrict__ Wv)
{
    int gw = (blockIdx.x * blockDim.x + threadIdx.x) >> 5;
    int lane = threadIdx.x & 31;
    int b = gw >> 10;
    int od = gw & 1023;           // h*64+d
    int h = od >> 6;
    const float* vb = g_vbar + (size_t)(b * Hdim + h) * Edim;
    const float* wr = Wv + (size_t)od * Edim;
    float s = 0.f;
    for (int e = lane * 4; e < Edim; e += 128) {
        float4 w4 = *(const float4*)&wr[e];
        float4 v4 = *(const float4*)&vb[e];
        s = fmaf(w4.x, v4.x, s);
        s = fmaf(w4.y, v4.y, s);
        s = fmaf(w4.z, v4.z, s);
        s = fmaf(w4.w, v4.w, s);
    }
#pragma unroll
    for (int off = 16; off; off >>= 1) s += __shfl_xor_sync(0xffffffffu, s, off);
    if (lane == 0) g_ho[(size_t)b * Edim + od] = s;
}

// ======================================================================
// Final: out[b, e'] = sum_e ho[b, e] * Wo[e', e]   (warp per output)
// ======================================================================
__global__ void __launch_bounds__(256) out_kernel(const float* __restrict__ Wo,
                                                  float* __restrict__ out)
{
    int gw = (blockIdx.x * blockDim.x + threadIdx.x) >> 5;
    int lane = threadIdx.x & 31;
    int b = gw >> 10;
    int ep = gw & 1023;
    const float* ho = &g_ho[(size_t)b * Edim];
    const float* wr = &Wo[(size_t)ep * Edim];
    float s = 0.f;
    for (int e = lane * 4; e < Edim; e += 128) {
        float4 w4 = *(const float4*)&wr[e];
        float4 h4 = *(const float4*)&ho[e];
        s = fmaf(w4.x, h4.x, s);
        s = fmaf(w4.y, h4.y, s);
        s = fmaf(w4.z, h4.z, s);
        s = fmaf(w4.w, h4.w, s);
    }
#pragma unroll
    for (int off = 16; off; off >>= 1) s += __shfl_xor_sync(0xffffffffu, s, off);
    if (lane == 0) out[(size_t)b * Edim + ep] = s;
}

// ======================================================================
extern "C" void kernel_launch(void* const* d_in, const int* in_sizes, int n_in,
                              void* d_out, int out_size)
{
    const float* Q = (const float*)d_in[0];
    const float* K = (const float*)d_in[1];
    const float* V = (const float*)d_in[2];
    const float* Wq = (const float*)d_in[3];
    const float* Wk = (const float*)d_in[4];
    const float* Wv = (const float*)d_in[5];
    const float* Wo = (const float*)d_in[6];
    float* out = (float*)d_out;

    cudaFuncSetAttribute(proj_mma_kernel, cudaFuncAttributeMaxDynamicSharedMemorySize, PJ_SMEM_BYTES);
    cudaFuncSetAttribute(attn_passA_kernel, cudaFuncAttributeMaxDynamicSharedMemorySize, A_SMEM_BYTES);

    zero_acc_kernel<<<64, 1024>>>();
    proj_mma_kernel<<<dim3(NROWS / 128, Edim / 128, 2), 256, PJ_SMEM_BYTES>>>(Q, K, Wq, Wk);
    attn_passA_kernel<<<dim3(Ldim / 128, NBH), 256, A_SMEM_BYTES>>>();
    vbar_kernel<<<dim3(Edim / 256, Bdim, Ldim / 128), 256>>>(V);
    ho_kernel<<<256, 256>>>(Wv);
    out_kernel<<<256, 256>>>(Wo, out);
}

// round 17
// speedup vs baseline: 1.0761x; 1.0761x over previous
#include <cuda_runtime.h>
#include <cuda_bf16.h>
#include <cuda_fp16.h>
#include <math.h>
#include <cstdint>

#define Bdim 2
#define Ldim 2048
#define Edim 1024
#define Hdim 16
#define Ddim 64
#define NROWS (Bdim * Ldim)  // 4096
#define NBH (Bdim * Hdim)    // 32

// log2(e)^2 folding: C2*d2 inside sqrt gives log2(e)*d directly
#define C2 2.0813689810056077f
#define NEG2C2 (-4.1627379620112154f)

// Scratch (allocation-free rule: __device__ globals)
__device__ unsigned short g_qh[(size_t)NROWS * Edim];       // q proj, bf16, row-major (B,L,E)
__device__ unsigned short g_kh[(size_t)NROWS * Edim];       // k proj, bf16, row-major (B,L,E)
__device__ float g_q2[NBH * Ldim];                // C2 * ||q||^2 (fp32-derived, accumulated)
__device__ float g_k2[NBH * Ldim];                // C2 * ||k||^2
__device__ float g_invZ[NBH * Ldim];
__device__ float g_w[NBH * Ldim];
__device__ float g_vbar[NBH * Edim];              // Σ_k w[bh,k] * V[b,k,:]  (exact fp32)
__device__ float g_ho[Bdim * Edim];
// exp scores, f16, scaled 4096x. k-PERMUTED within each 32-col block:
//   pos = t*8 + ni*2 + j  holds  k = ni*8 + 2t + j
__device__ unsigned short g_e[(size_t)NBH * Ldim * Ldim];

// ======================================================================
// Helpers (plain sm_103 target: mma.sync + cp.async only)
// ======================================================================
__device__ __forceinline__ uint32_t smem_to_u32(const void* smem_ptr) {
    uint32_t addr;
    asm("{ .reg .u64 tmp; cvta.to.shared.u64 tmp, %1; cvt.u32.u64 %0, tmp; }"
        : "=r"(addr) : "l"(smem_ptr));
    return addr;
}
__device__ __forceinline__ void cp_async16(uint32_t s, const void* g) {
    asm volatile("cp.async.cg.shared.global [%0], [%1], 16;" :: "r"(s), "l"(g) : "memory");
}
__device__ __forceinline__ void cp_commit() {
    asm volatile("cp.async.commit_group;" ::: "memory");
}
template <int N>
__device__ __forceinline__ void cp_wait() {
    asm volatile("cp.async.wait_group %0;" :: "n"(N) : "memory");
}
__device__ __forceinline__ uint32_t f2tf(float x) {
    uint32_t r;
    asm("cvt.rna.tf32.f32 %0, %1;" : "=r"(r) : "f"(x));
    return r;
}
__device__ __forceinline__ float fast_sqrt(float x) {
    float r; asm("sqrt.approx.f32 %0, %1;" : "=f"(r) : "f"(x)); return r;
}
// packed f16x2 exp2 — one MUFU op, two results. Arg quantization error is
// incoherent per (q,k) -> averages out in w (verified R7==R8, R9..R15 pass).
__device__ __forceinline__ uint32_t h2_ex2(uint32_t x) {
    uint32_t r;
    asm("ex2.approx.f16x2 %0, %1;" : "=r"(r) : "r"(x));
    return r;
}
__device__ __forceinline__ void mma_tf32(float c[4], const uint32_t a[4], const uint32_t b[2]) {
    asm volatile(
        "mma.sync.aligned.m16n8k8.row.col.f32.tf32.tf32.f32 "
        "{%0,%1,%2,%3}, {%4,%5,%6,%7}, {%8,%9}, {%0,%1,%2,%3};"
        : "+f"(c[0]), "+f"(c[1]), "+f"(c[2]), "+f"(c[3])
        : "r"(a[0]), "r"(a[1]), "r"(a[2]), "r"(a[3]), "r"(b[0]), "r"(b[1]));
}
__device__ __forceinline__ void mma_bf16(float c[4], const uint32_t a[4], const uint32_t b[2]) {
    asm volatile(
        "mma.sync.aligned.m16n8k16.row.col.f32.bf16.bf16.f32 "
        "{%0,%1,%2,%3}, {%4,%5,%6,%7}, {%8,%9}, {%0,%1,%2,%3};"
        : "+f"(c[0]), "+f"(c[1]), "+f"(c[2]), "+f"(c[3])
        : "r"(a[0]), "r"(a[1]), "r"(a[2]), "r"(a[3]), "r"(b[0]), "r"(b[1]));
}

// ======================================================================
// Zero accumulators: g_ho, g_w, g_q2, g_k2, g_vbar (runs FIRST)
// ======================================================================
__global__ void zero_acc_kernel()
{
    int i = blockIdx.x * blockDim.x + threadIdx.x;  // 0..65535
    if (i < Bdim * Edim) g_ho[i] = 0.f;
    if (i < NBH * Edim) g_vbar[i] = 0.f;
    g_w[i] = 0.f;
    g_q2[i] = 0.f;
    g_k2[i] = 0.f;
}

// ======================================================================
// Projection GEMM (mma.sync tf32, inline rna cvt — R10 config).
// ONLY q (z=0) and k (z=1): V projection eliminated algebraically.
// Epilogue writes bf16 row-major + accumulates C2*||.||^2 via atomics.
// ======================================================================
#define PJST 36
#define PJ_TILE_FLOATS (128 * PJST)
#define PJ_BUF_FLOATS (2 * PJ_TILE_FLOATS)
#define PJ_SMEM_BYTES (2 * PJ_BUF_FLOATS * 4 + 1024)

__global__ void __launch_bounds__(256) proj_mma_kernel(
    const float* __restrict__ Q, const float* __restrict__ K,
    const float* __restrict__ Wq, const float* __restrict__ Wk)
{
    extern __shared__ float smem[];
    const uint32_t smem_u32 = smem_to_u32(smem);

    const int z = blockIdx.z;
    const float* __restrict__ X = z ? K : Q;
    const float* __restrict__ W = z ? Wk : Wq;
    const int m0 = blockIdx.x * 128;
    const int n0 = blockIdx.y * 128;

    const int tid = threadIdx.x;
    const int wid = tid >> 5;
    const int lane = tid & 31;
    const int g = lane >> 2;
    const int t = lane & 3;
    const int wm = (wid >> 2) * 64;
    const int wn = (wid & 3) * 32;

    float c[4][4][4];
#pragma unroll
    for (int mi = 0; mi < 4; mi++)
#pragma unroll
        for (int ni = 0; ni < 4; ni++)
#pragma unroll
            for (int r = 0; r < 4; r++) c[mi][ni][r] = 0.f;

    auto load_chunk = [&](int cc) {
        const int k0 = cc * 32;
        uint32_t abase = smem_u32 + (uint32_t)((cc & 1) * PJ_BUF_FLOATS) * 4u;
#pragma unroll
        for (int it = 0; it < 4; it++) {
            int idx = tid + it * 256;
            int row = idx >> 3;
            int q = idx & 7;
            uint32_t soff = (uint32_t)(row * PJST + q * 4) * 4u;
            cp_async16(abase + soff, &X[(size_t)(m0 + row) * Edim + k0 + q * 4]);
            cp_async16(abase + (uint32_t)PJ_TILE_FLOATS * 4u + soff,
                       &W[(size_t)(n0 + row) * Edim + k0 + q * 4]);
        }
        cp_commit();
    };

    load_chunk(0);

    for (int cc = 0; cc < 32; cc++) {
        if (cc + 1 < 32) {
            load_chunk(cc + 1);
            cp_wait<1>();
        } else {
            cp_wait<0>();
        }
        __syncthreads();

        const float* As_ = smem + (cc & 1) * PJ_BUF_FLOATS;
        const float* Bs_ = As_ + PJ_TILE_FLOATS;

#pragma unroll
        for (int ks = 0; ks < 4; ks++) {
            const int k0 = ks * 8;
            uint32_t a[4][4], bf[4][2];
#pragma unroll
            for (int mi = 0; mi < 4; mi++) {
                const float* ap = As_ + (wm + mi * 16 + g) * PJST + k0 + t;
                a[mi][0] = f2tf(ap[0]);
                a[mi][1] = f2tf(ap[8 * PJST]);
                a[mi][2] = f2tf(ap[4]);
                a[mi][3] = f2tf(ap[8 * PJST + 4]);
            }
#pragma unroll
            for (int ni = 0; ni < 4; ni++) {
                const float* bp = Bs_ + (wn + ni * 8 + g) * PJST + k0 + t;
                bf[ni][0] = f2tf(bp[0]);
                bf[ni][1] = f2tf(bp[4]);
            }
#pragma unroll
            for (int mi = 0; mi < 4; mi++)
#pragma unroll
                for (int ni = 0; ni < 4; ni++) mma_tf32(c[mi][ni], a[mi], bf[ni]);
        }
        __syncthreads();
    }

    unsigned short* dst = z ? g_kh : g_qh;
    float* nrm = z ? g_k2 : g_q2;
    float* snorm = smem;  // 256 floats: [row128][head_local]

    if (tid < 256) snorm[tid] = 0.f;

    float rsum[4][2];
#pragma unroll
    for (int mi = 0; mi < 4; mi++) {
#pragma unroll
        for (int half = 0; half < 2; half++) {
            float s = 0.f;
#pragma unroll
            for (int ni = 0; ni < 4; ni++) {
                float v0 = c[mi][ni][half * 2 + 0];
                float v1 = c[mi][ni][half * 2 + 1];
                s = fmaf(v0, v0, s);
                s = fmaf(v1, v1, s);
            }
            rsum[mi][half] = s;
        }
    }
#pragma unroll
    for (int mi = 0; mi < 4; mi++)
#pragma unroll
        for (int half = 0; half < 2; half++) {
            float s = rsum[mi][half];
            s += __shfl_xor_sync(0xffffffffu, s, 1);
            s += __shfl_xor_sync(0xffffffffu, s, 2);
            rsum[mi][half] = s;
        }
    __syncthreads();
    const int hh = wn >> 6;
    if (t == 0) {
#pragma unroll
        for (int mi = 0; mi < 4; mi++)
#pragma unroll
            for (int half = 0; half < 2; half++) {
                int r128 = wm + mi * 16 + half * 8 + g;
                atomicAdd(&snorm[r128 * 2 + hh], rsum[mi][half]);
            }
    }

#pragma unroll
    for (int mi = 0; mi < 4; mi++) {
        int row = m0 + wm + mi * 16 + g;
#pragma unroll
        for (int ni = 0; ni < 4; ni++) {
            int col = n0 + wn + ni * 8 + 2 * t;
            __nv_bfloat162 lo = __float22bfloat162_rn(make_float2(c[mi][ni][0], c[mi][ni][1]));
            __nv_bfloat162 hi = __float22bfloat162_rn(make_float2(c[mi][ni][2], c[mi][ni][3]));
            *(__nv_bfloat162*)&dst[(size_t)row * Edim + col] = lo;
            *(__nv_bfloat162*)&dst[(size_t)(row + 8) * Edim + col] = hi;
        }
    }

    __syncthreads();
    if (tid < 256) {
        int r128 = tid >> 1;
        int row = m0 + r128;
        int b = row >> 11;
        int l = row & 2047;
        int h = (n0 >> 6) + (tid & 1);
        atomicAdd(&nrm[(b * Hdim + h) * Ldim + l], C2 * snorm[tid]);
    }
}

// ======================================================================
// Attention pass A (R14/R15 exact): bf16 m16n8k16 QK^T; f16x2-MUFU exp;
// e stored k-permuted with 16B-contiguous per-thread uint4 STGs.
// ======================================================================
#define A_Q_BYTES (128 * 144)
#define A_K_BYTES (128 * 144)
#define A_SMEM_BYTES (A_Q_BYTES + 2 * A_K_BYTES + 512)

__global__ void __launch_bounds__(256, 2) attn_passA_kernel()
{
    extern __shared__ char smc[];
    char* qsc = smc;
    char* ksc = smc + A_Q_BYTES;
    float* zsh = (float*)(smc + A_Q_BYTES + 2 * A_K_BYTES);
    const uint32_t qs_u = smem_to_u32(qsc);
    const uint32_t ks_u = smem_to_u32(ksc);

    const int tid = threadIdx.x;
    const int wid = tid >> 5;
    const int lane = tid & 31;
    const int g = lane >> 2;
    const int t = lane & 3;
    const int wm = (wid >> 2) * 64;
    const int wn = (wid & 3) * 32;
    const int bh = blockIdx.y;
    const int b = bh >> 4;
    const int h = bh & 15;
    const int qbase = blockIdx.x * 128;

    if (tid < 128) zsh[tid] = 0.f;

    const unsigned short* gq = g_qh + (size_t)(b * Ldim + qbase) * Edim + h * Ddim;
    const unsigned short* gk = g_kh + (size_t)(b * Ldim) * Edim + h * Ddim;

#pragma unroll
    for (int it = 0; it < 4; it++) {
        int idx = tid + it * 256;
        int r = idx >> 3;
        int ch = idx & 7;
        cp_async16(qs_u + (uint32_t)(r * 144 + ch * 16), gq + (size_t)r * Edim + ch * 8);
    }
    cp_commit();

    auto load_k = [&](int jt) {
        uint32_t base = ks_u + (uint32_t)((jt & 1) * A_K_BYTES);
#pragma unroll
        for (int it = 0; it < 4; it++) {
            int idx = tid + it * 256;
            int r = idx >> 3;
            int ch = idx & 7;
            cp_async16(base + (uint32_t)(r * 144 + ch * 16),
                       gk + (size_t)(jt * 128 + r) * Edim + ch * 8);
        }
        cp_commit();
    };

    load_k(0);
    cp_wait<1>();
    __syncthreads();

    float q2r[8];
    const float* q2p = g_q2 + bh * Ldim + qbase;
#pragma unroll
    for (int i = 0; i < 8; i++) q2r[i] = q2p[wm + (i >> 1) * 16 + (i & 1) * 8 + g];

    unsigned short* pe0 = g_e + ((size_t)bh * Ldim + qbase + wm + g) * Ldim + wn + t * 8;

    float zloc[8];
#pragma unroll
    for (int i = 0; i < 8; i++) zloc[i] = 0.f;

    for (int jt = 0; jt < 16; jt++) {
        if (jt + 1 < 16) {
            load_k(jt + 1);
            cp_wait<1>();
        } else {
            cp_wait<0>();
        }
        __syncthreads();

        const char* kb = ksc + (jt & 1) * A_K_BYTES;

        float c[4][4][4];
#pragma unroll
        for (int mi = 0; mi < 4; mi++)
#pragma unroll
            for (int ni = 0; ni < 4; ni++)
#pragma unroll
                for (int r = 0; r < 4; r++) c[mi][ni][r] = 0.f;

#pragma unroll
        for (int ks = 0; ks < 4; ks++) {
            uint32_t a[4][4], bf[4][2];
#pragma unroll
            for (int mi = 0; mi < 4; mi++) {
                const char* ap = qsc + (wm + mi * 16 + g) * 144 + ks * 32 + t * 4;
                a[mi][0] = *(const uint32_t*)(ap);
                a[mi][1] = *(const uint32_t*)(ap + 8 * 144);
                a[mi][2] = *(const uint32_t*)(ap + 16);
                a[mi][3] = *(const uint32_t*)(ap + 8 * 144 + 16);
            }
#pragma unroll
            for (int ni = 0; ni < 4; ni++) {
                const char* bp = kb + (wn + ni * 8 + g) * 144 + ks * 32 + t * 4;
                bf[ni][0] = *(const uint32_t*)(bp);
                bf[ni][1] = *(const uint32_t*)(bp + 16);
            }
#pragma unroll
            for (int mi = 0; mi < 4; mi++)
#pragma unroll
                for (int ni = 0; ni < 4; ni++) mma_bf16(c[mi][ni], a[mi], bf[ni]);
        }

        const float* k2p = g_k2 + bh * Ldim + jt * 128;
        unsigned short* pet = pe0 + jt * 128;
        float2 k2c[4];
#pragma unroll
        for (int ni = 0; ni < 4; ni++) k2c[ni] = *(const float2*)&k2p[wn + ni * 8 + 2 * t];
#pragma unroll
        for (int mi = 0; mi < 4; mi++) {
#pragma unroll
            for (int half = 0; half < 2; half++) {
                uint32_t ee4[4];
                float zz = 0.f;
#pragma unroll
                for (int ni = 0; ni < 4; ni++) {
                    float s0 = fmaf(NEG2C2, c[mi][ni][half * 2 + 0], q2r[mi * 2 + half] + k2c[ni].x);
                    float s1 = fmaf(NEG2C2, c[mi][ni][half * 2 + 1], q2r[mi * 2 + half] + k2c[ni].y);
                    float a0 = 12.f - fast_sqrt(fmaxf(s0, 0.f));
                    float a1 = 12.f - fast_sqrt(fmaxf(s1, 0.f));
                    __half2 hh2 = __floats2half2_rn(a0, a1);
                    uint32_t ee = h2_ex2(*(const uint32_t*)&hh2);
                    float2 ef = __half22float2(*(const __half2*)&ee);
                    zz += ef.x + ef.y;
                    ee4[ni] = ee;
                }
                zloc[mi * 2 + half] += zz;
                *(uint4*)(pet + (size_t)(mi * 16 + half * 8) * Ldim) =
                    make_uint4(ee4[0], ee4[1], ee4[2], ee4[3]);
            }
        }
        __syncthreads();
    }

#pragma unroll
    for (int i = 0; i < 8; i++) {
        float z = zloc[i];
        z += __shfl_xor_sync(0xffffffffu, z, 1);
        z += __shfl_xor_sync(0xffffffffu, z, 2);
        if (t == 0) atomicAdd(&zsh[wm + (i >> 1) * 16 + (i & 1) * 8 + g], z);
    }
    __syncthreads();
    if (tid < 128) g_invZ[bh * Ldim + qbase + tid] = 1.f / zsh[tid];
}

// ======================================================================
// Pass B (R14/R15 exact): w_k = sum_q e'[q][k] * invZ'[q]; un-permutes at
// the final scalar atomicAdd. Standalone kernel @2048 CTAs = 78% DRAM
// (R16 proved fusing this into passA's tail LOSES ~12us).
// ======================================================================
__global__ void __launch_bounds__(256) attn_passB_kernel()
{
    __shared__ float invz[512];
    __shared__ float wsm[8][128];

    const int tid = threadIdx.x;
    const int wid = tid >> 5;
    const int lane = tid & 31;
    const int bh = blockIdx.y;
    const int kbase = blockIdx.x * 128;
    const int qslice = blockIdx.z * 512;

    for (int i = tid; i < 512; i += 256) invz[i] = g_invZ[bh * Ldim + qslice + i];
    __syncthreads();

    const unsigned short* pe =
        g_e + ((size_t)bh * Ldim + qslice + wid) * Ldim + kbase + lane * 4;

    float acc[4];
#pragma unroll
    for (int j = 0; j < 4; j++) acc[j] = 0.f;

#pragma unroll 8
    for (int q = wid; q < 512; q += 8) {
        uint2 raw = *(const uint2*)pe;
        float iz = invz[q];
        float2 e0 = __half22float2(*(const __half2*)&raw.x);
        float2 e1 = __half22float2(*(const __half2*)&raw.y);
        acc[0] = fmaf(e0.x, iz, acc[0]);
        acc[1] = fmaf(e0.y, iz, acc[1]);
        acc[2] = fmaf(e1.x, iz, acc[2]);
        acc[3] = fmaf(e1.y, iz, acc[3]);
        pe += (size_t)8 * Ldim;
    }
#pragma unroll
    for (int j = 0; j < 4; j++) wsm[wid][lane * 4 + j] = acc[j];
    __syncthreads();
    if (tid < 128) {
        float s = 0.f;
#pragma unroll
        for (int wq = 0; wq < 8; wq++) s += wsm[wq][tid];
        int blk = tid >> 5;
        int pos = tid & 31;
        int pt = pos >> 3;
        int r = pos & 7;
        int kk = (r >> 1) * 8 + pt * 2 + (r & 1);
        atomicAdd(&g_w[bh * Ldim + kbase + blk * 32 + kk], s);
    }
}

// ======================================================================
// vbar[b,h,e] = sum_k w[bh,k] * V[b,k,e]   (raw fp32 V — no projection!)
// R16 ncu: 128 CTAs / occ 12% / DRAM 8% -> latency-bound. Now 64 k-slices
// of 32 rows -> 512 CTAs (~3.5/SM) + unroll 8 for MLP. Atomics x4 (fine).
// ======================================================================
__global__ void __launch_bounds__(256) vbar_kernel(const float* __restrict__ V)
{
    __shared__ float wsh[16][32];
    const int tid = threadIdx.x;
    const int e = blockIdx.x * 256 + tid;
    const int b = blockIdx.y;
    const int k0 = blockIdx.z * 32;

    for (int i = tid; i < 16 * 32; i += 256) {
        int h = i >> 5;
        int kk = i & 31;
        wsh[h][kk] = g_w[(b * Hdim + h) * Ldim + k0 + kk];
    }
    __syncthreads();

    float acc[16];
#pragma unroll
    for (int h = 0; h < 16; h++) acc[h] = 0.f;

    const float* vp = V + ((size_t)(b * Ldim + k0)) * Edim + e;
#pragma unroll 8
    for (int kk = 0; kk < 32; kk++) {
        float v = vp[(size_t)kk * Edim];
#pragma unroll
        for (int h = 0; h < 16; h++) acc[h] = fmaf(wsh[h][kk], v, acc[h]);
    }
#pragma unroll
    for (int h = 0; h < 16; h++)
        atomicAdd(&g_vbar[(b * Hdim + h) * Edim + e], acc[h]);
}

// ======================================================================
// ho[b, h*64+d] = vbar[b,h,:] . Wv[h*64+d,:]   (warp per output, fp32)
// ======================================================================
__global__ void __launch_bounds__(256) ho_kernel(const float* __restrict__ Wv)
{
    int gw = (blockIdx.x * blockDim.x + threadIdx.x) >> 5;
    int lane = threadIdx.x & 31;
    int b = gw >> 10;
    int od = gw & 1023;           // h*64+d
    int h = od >> 6;
    const float* vb = g_vbar + (size_t)(b * Hdim + h) * Edim;
    const float* wr = Wv + (size_t)od * Edim;
    float s = 0.f;
    for (int e = lane * 4; e < Edim; e += 128) {
        float4 w4 = *(const float4*)&wr[e];
        float4 v4 = *(const float4*)&vb[e];
        s = fmaf(w4.x, v4.x, s);
        s = fmaf(w4.y, v4.y, s);
        s = fmaf(w4.z, v4.z, s);
        s = fmaf(w4.w, v4.w, s);
    }
#pragma unroll
    for (int off = 16; off; off >>= 1) s += __shfl_xor_sync(0xffffffffu, s, off);
    if (lane == 0) g_ho[(size_t)b * Edim + od] = s;
}

// ======================================================================
// Final: out[b, e'] = sum_e ho[b, e] * Wo[e', e]   (warp per output)
// ======================================================================
__global__ void __launch_bounds__(256) out_kernel(const float* __restrict__ Wo,
                                                  float* __restrict__ out)
{
    int gw = (blockIdx.x * blockDim.x + threadIdx.x) >> 5;
    int lane = threadIdx.x & 31;
    int b = gw >> 10;
    int ep = gw & 1023;
    const float* ho = &g_ho[(size_t)b * Edim];
    const float* wr = &Wo[(size_t)ep * Edim];
    float s = 0.f;
    for (int e = lane * 4; e < Edim; e += 128) {
        float4 w4 = *(const float4*)&wr[e];
        float4 h4 = *(const float4*)&ho[e];
        s = fmaf(w4.x, h4.x, s);
        s = fmaf(w4.y, h4.y, s);
        s = fmaf(w4.z, h4.z, s);
        s = fmaf(w4.w, h4.w, s);
    }
#pragma unroll
    for (int off = 16; off; off >>= 1) s += __shfl_xor_sync(0xffffffffu, s, off);
    if (lane == 0) out[(size_t)b * Edim + ep] = s;
}

// ======================================================================
extern "C" void kernel_launch(void* const* d_in, const int* in_sizes, int n_in,
                              void* d_out, int out_size)
{
    const float* Q = (const float*)d_in[0];
    const float* K = (const float*)d_in[1];
    const float* V = (const float*)d_in[2];
    const float* Wq = (const float*)d_in[3];
    const float* Wk = (const float*)d_in[4];
    const float* Wv = (const float*)d_in[5];
    const float* Wo = (const float*)d_in[6];
    float* out = (float*)d_out;

    cudaFuncSetAttribute(proj_mma_kernel, cudaFuncAttributeMaxDynamicSharedMemorySize, PJ_SMEM_BYTES);
    cudaFuncSetAttribute(attn_passA_kernel, cudaFuncAttributeMaxDynamicSharedMemorySize, A_SMEM_BYTES);

    zero_acc_kernel<<<64, 1024>>>();
    proj_mma_kernel<<<dim3(NROWS / 128, Edim / 128, 2), 256, PJ_SMEM_BYTES>>>(Q, K, Wq, Wk);
    attn_passA_kernel<<<dim3(Ldim / 128, NBH), 256, A_SMEM_BYTES>>>();
    attn_passB_kernel<<<dim3(Ldim / 128, NBH, 4), 256>>>();
    vbar_kernel<<<dim3(Edim / 256, Bdim, Ldim / 32), 256>>>(V);
    ho_kernel<<<256, 256>>>(Wv);
    out_kernel<<<256, 256>>>(Wo, out);
}